// round 14
// baseline (speedup 1.0000x reference)
#include <cuda_runtime.h>
#include <cuda_bf16.h>
#include <math.h>

#define NN   50000
#define EE   800000
#define ETOT 850000          // EE + NN self loops
#define FDIM 128
#define HEADS 4
#define HC   256
#define NG   64
#define NEG_SLOPE 0.2f
#define BN_EPS 1e-5f
#define DEG_CAP 128
#define NPB 8                // nodes per aggregate block (1 per warp)

// ---------------- scratch (device globals: allocation-free) ----------------
// Invariants maintained across runs: g_deg == 0 (restored by scan_kernel),
// g_pooled == 0 (restored by mlp_kernel). Both start zeroed at module load.
__device__ __align__(16) __nv_bfloat16 g_h16[(size_t)NN * HC];  // GEMM output (bf16)
__device__ __align__(16) __nv_bfloat16 g_hB[(size_t)NN * HC];   // aggregate output (bf16)
__device__ float g_ssrc[NN * HEADS];
__device__ float g_sdst[NN * HEADS];
__device__ float g_ex[(size_t)ETOT * HEADS];  // deg > DEG_CAP spill
__device__ int   g_deg[NN];
__device__ int   g_rowptr[NN + 1];
__device__ int   g_cursor[NN];
__device__ int   g_csrc[ETOT];
__device__ float g_pooled[NG * HC];

__device__ __forceinline__ unsigned packbf(float a, float b) {
    __nv_bfloat162 h = __floats2bfloat162_rn(a, b);
    return *(unsigned*)&h;
}

// ---------------- CSR build ----------------
// count over the EE real edges only (self-loops handled in scan)
__global__ void count_kernel(const int* __restrict__ ei) {
    int e = blockIdx.x * blockDim.x + threadIdx.x;
    if (e >= EE) return;
    atomicAdd(&g_deg[ei[EE + e]], 1);
}

// 1024-thread block scan; also writes each node's self-loop CSR entry and
// re-zeroes g_deg (self-cleaning invariant).
__global__ void scan_kernel() {
    __shared__ int wsum[32];
    const int PER = (NN + 1023) / 1024;  // 49
    int tid = threadIdx.x;
    int lane = tid & 31, w = tid >> 5;
    int base = tid * PER;

    int sum = 0;
    for (int i = 0; i < PER; i++) {
        int idx = base + i;
        if (idx < NN) sum += g_deg[idx] + 1;   // +1 self loop
    }
    int v = sum;
    #pragma unroll
    for (int off = 1; off < 32; off <<= 1) {
        int x = __shfl_up_sync(0xffffffffu, v, off);
        if (lane >= off) v += x;
    }
    if (lane == 31) wsum[w] = v;
    __syncthreads();
    if (w == 0) {
        int s = wsum[lane];
        #pragma unroll
        for (int off = 1; off < 32; off <<= 1) {
            int x = __shfl_up_sync(0xffffffffu, s, off);
            if (lane >= off) s += x;
        }
        wsum[lane] = s;
    }
    __syncthreads();
    int excl = v - sum + ((w > 0) ? wsum[w - 1] : 0);
    int run = excl;
    for (int i = 0; i < PER; i++) {
        int idx = base + i;
        if (idx < NN) {
            int d = g_deg[idx];
            g_rowptr[idx] = run;
            g_cursor[idx] = run;         // fill atomics take slots run..run+d-1
            g_csrc[run + d] = idx;       // self-loop in the last slot
            g_deg[idx] = 0;              // restore invariant
            run += d + 1;
        }
    }
    if (tid == 1023) g_rowptr[NN] = run;
}

__global__ void fill_kernel(const int* __restrict__ ei) {
    int e = blockIdx.x * blockDim.x + threadIdx.x;
    if (e >= EE) return;
    int s = ei[e];
    int d = ei[EE + e];
    int pos = atomicAdd(&g_cursor[d], 1);
    g_csrc[pos] = s;
}

// ---------------- tf32 tensor-core GEMM + fused attention scalars ----------------
// C16[M,256] = bf16(A[M,K] @ B[K,256]); also s_src/s_dst per (row, head).
// A source is fp32 (Af) or bf16 (Ah); exactly one non-null. bf16 values are
// exactly representable in tf32, so the Ah path needs no tf32 rounding.
__device__ __forceinline__ float tf32r(float x) {
    unsigned u;
    asm("cvt.rna.tf32.f32 %0, %1;" : "=r"(u) : "f"(x));
    return __uint_as_float(u);
}
__device__ __forceinline__ float4 tf32r4(float4 v) {
    return make_float4(tf32r(v.x), tf32r(v.y), tf32r(v.z), tf32r(v.w));
}
__device__ __forceinline__ void mma_tf32(float* c, const unsigned* a, const unsigned* b) {
    asm volatile(
        "mma.sync.aligned.m16n8k8.row.col.f32.tf32.tf32.f32 "
        "{%0,%1,%2,%3}, {%4,%5,%6,%7}, {%8,%9}, {%0,%1,%2,%3};"
        : "+f"(c[0]), "+f"(c[1]), "+f"(c[2]), "+f"(c[3])
        : "r"(a[0]), "r"(a[1]), "r"(a[2]), "r"(a[3]), "r"(b[0]), "r"(b[1]));
}

#define ASTRIDE 20    // floats per A smem row (conflict-free frag loads, 16B aligned)
#define BSTRIDE 136   // floats per B smem k-row

__global__ __launch_bounds__(256, 2) void gemm_tf32_kernel(
    const float* __restrict__ Af, const __nv_bfloat16* __restrict__ Ah,
    const float* __restrict__ B,
    __nv_bfloat16* __restrict__ C16,
    const float* __restrict__ asrc, const float* __restrict__ adst,
    int M, int K)
{
    __shared__ float As[2][128][ASTRIDE];
    __shared__ float Bs[2][16][BSTRIDE];
    __shared__ float sh_s[128][2];
    __shared__ float sh_d[128][2];

    int t = threadIdx.x;
    int lane = t & 31, wid = t >> 5;
    int gid = lane >> 2, tig = lane & 3;
    int warp_m = (wid & 1) * 64;
    int warp_n = (wid >> 1) * 32;
    int brow = blockIdx.x * 128;
    int bcol = blockIdx.y * 128;

    if (t < 128) { sh_s[t][0] = 0.f; sh_s[t][1] = 0.f; sh_d[t][0] = 0.f; sh_d[t][1] = 0.f; }

    float acc[4][4][4];
    #pragma unroll
    for (int mt = 0; mt < 4; mt++)
        #pragma unroll
        for (int nt = 0; nt < 4; nt++)
            #pragma unroll
            for (int q = 0; q < 4; q++) acc[mt][nt][q] = 0.f;

    int am = t >> 1;
    int ah = (t & 1) * 8;
    int grA = brow + am;
    bool arow_ok = (grA < M);
    bool a_bf = (Ah != nullptr);
    int i0 = t, i1 = t + 256;
    int bk0 = i0 >> 5, bn0 = i0 & 31;
    int bk1 = i1 >> 5, bn1 = i1 & 31;

    float4 av0, av1, bv0, bv1;
    const float4 zero4 = make_float4(0.f, 0.f, 0.f, 0.f);

    int nk = K >> 4;

    // prefetch tile 0 (A path branches on dtype, inline)
    {
        if (a_bf) {
            if (arow_ok) {
                uint4 vv = *(const uint4*)(Ah + (size_t)grA * K + ah);
                float2 f0 = __bfloat1622float2(*(__nv_bfloat162*)&vv.x);
                float2 f1 = __bfloat1622float2(*(__nv_bfloat162*)&vv.y);
                float2 f2 = __bfloat1622float2(*(__nv_bfloat162*)&vv.z);
                float2 f3 = __bfloat1622float2(*(__nv_bfloat162*)&vv.w);
                av0 = make_float4(f0.x, f0.y, f1.x, f1.y);
                av1 = make_float4(f2.x, f2.y, f3.x, f3.y);
            } else { av0 = zero4; av1 = zero4; }
        } else {
            av0 = arow_ok ? tf32r4(*(const float4*)(Af + (size_t)grA * K + ah))     : zero4;
            av1 = arow_ok ? tf32r4(*(const float4*)(Af + (size_t)grA * K + ah + 4)) : zero4;
        }
        bv0 = *(const float4*)&B[(size_t)bk0 * HC + bcol + bn0 * 4];
        bv1 = *(const float4*)&B[(size_t)bk1 * HC + bcol + bn1 * 4];
        *(float4*)&As[0][am][ah]     = av0;
        *(float4*)&As[0][am][ah + 4] = av1;
        *(float4*)&Bs[0][bk0][bn0 * 4] = tf32r4(bv0);
        *(float4*)&Bs[0][bk1][bn1 * 4] = tf32r4(bv1);
    }

    for (int kb = 0; kb < nk; kb++) {
        __syncthreads();
        int cur = kb & 1;
        if (kb + 1 < nk) {
            int k0 = (kb + 1) * 16;
            if (a_bf) {
                if (arow_ok) {
                    uint4 vv = *(const uint4*)(Ah + (size_t)grA * K + k0 + ah);
                    float2 f0 = __bfloat1622float2(*(__nv_bfloat162*)&vv.x);
                    float2 f1 = __bfloat1622float2(*(__nv_bfloat162*)&vv.y);
                    float2 f2 = __bfloat1622float2(*(__nv_bfloat162*)&vv.z);
                    float2 f3 = __bfloat1622float2(*(__nv_bfloat162*)&vv.w);
                    av0 = make_float4(f0.x, f0.y, f1.x, f1.y);
                    av1 = make_float4(f2.x, f2.y, f3.x, f3.y);
                } else { av0 = zero4; av1 = zero4; }
            } else {
                av0 = arow_ok ? tf32r4(*(const float4*)(Af + (size_t)grA * K + k0 + ah))     : zero4;
                av1 = arow_ok ? tf32r4(*(const float4*)(Af + (size_t)grA * K + k0 + ah + 4)) : zero4;
            }
            bv0 = *(const float4*)&B[(size_t)(k0 + bk0) * HC + bcol + bn0 * 4];
            bv1 = *(const float4*)&B[(size_t)(k0 + bk1) * HC + bcol + bn1 * 4];
        }
        #pragma unroll
        for (int c = 0; c < 2; c++) {
            unsigned afrag[4][4], bfrag[4][2];
            #pragma unroll
            for (int mt = 0; mt < 4; mt++) {
                int r = warp_m + mt * 16 + gid;
                afrag[mt][0] = __float_as_uint(As[cur][r][c * 8 + tig]);
                afrag[mt][1] = __float_as_uint(As[cur][r + 8][c * 8 + tig]);
                afrag[mt][2] = __float_as_uint(As[cur][r][c * 8 + tig + 4]);
                afrag[mt][3] = __float_as_uint(As[cur][r + 8][c * 8 + tig + 4]);
            }
            #pragma unroll
            for (int nt = 0; nt < 4; nt++) {
                int cc = warp_n + nt * 8 + gid;
                bfrag[nt][0] = __float_as_uint(Bs[cur][c * 8 + tig][cc]);
                bfrag[nt][1] = __float_as_uint(Bs[cur][c * 8 + tig + 4][cc]);
            }
            #pragma unroll
            for (int mt = 0; mt < 4; mt++)
                #pragma unroll
                for (int nt = 0; nt < 4; nt++)
                    mma_tf32(acc[mt][nt], afrag[mt], bfrag[nt]);
        }
        if (kb + 1 < nk) {
            int nb = cur ^ 1;
            *(float4*)&As[nb][am][ah]     = av0;
            *(float4*)&As[nb][am][ah + 4] = av1;
            *(float4*)&Bs[nb][bk0][bn0 * 4] = tf32r4(bv0);
            *(float4*)&Bs[nb][bk1][bn1 * 4] = tf32r4(bv1);
        }
    }

    // ---- epilogue part 1: bf16 feature store ----
    #pragma unroll
    for (int mt = 0; mt < 4; mt++) {
        int r0 = brow + warp_m + mt * 16 + gid;
        int r1 = r0 + 8;
        #pragma unroll
        for (int nt = 0; nt < 4; nt++) {
            int col = bcol + warp_n + nt * 8 + tig * 2;
            if (r0 < M) *(__nv_bfloat162*)&C16[(size_t)r0 * HC + col] =
                __floats2bfloat162_rn(acc[mt][nt][0], acc[mt][nt][1]);
            if (r1 < M) *(__nv_bfloat162*)&C16[(size_t)r1 * HC + col] =
                __floats2bfloat162_rn(acc[mt][nt][2], acc[mt][nt][3]);
        }
    }

    // ---- epilogue part 2: fused attention scalars ----
    float as0[4], as1[4], ad0[4], ad1[4];
    #pragma unroll
    for (int nt = 0; nt < 4; nt++) {
        int col = bcol + warp_n + nt * 8 + tig * 2;
        as0[nt] = asrc[col]; as1[nt] = asrc[col + 1];
        ad0[nt] = adst[col]; ad1[nt] = adst[col + 1];
    }
    #pragma unroll
    for (int mt = 0; mt < 4; mt++) {
        float ps0 = 0.f, pd0 = 0.f, ps1 = 0.f, pd1 = 0.f;
        #pragma unroll
        for (int nt = 0; nt < 4; nt++) {
            ps0 += acc[mt][nt][0] * as0[nt] + acc[mt][nt][1] * as1[nt];
            pd0 += acc[mt][nt][0] * ad0[nt] + acc[mt][nt][1] * ad1[nt];
            ps1 += acc[mt][nt][2] * as0[nt] + acc[mt][nt][3] * as1[nt];
            pd1 += acc[mt][nt][2] * ad0[nt] + acc[mt][nt][3] * ad1[nt];
        }
        #pragma unroll
        for (int off = 1; off < 4; off <<= 1) {
            ps0 += __shfl_xor_sync(0xffffffffu, ps0, off);
            pd0 += __shfl_xor_sync(0xffffffffu, pd0, off);
            ps1 += __shfl_xor_sync(0xffffffffu, ps1, off);
            pd1 += __shfl_xor_sync(0xffffffffu, pd1, off);
        }
        if (tig == 0) {
            int hl = warp_n >> 6;
            int lr0 = warp_m + mt * 16 + gid;
            int lr1 = lr0 + 8;
            atomicAdd(&sh_s[lr0][hl], ps0);
            atomicAdd(&sh_d[lr0][hl], pd0);
            atomicAdd(&sh_s[lr1][hl], ps1);
            atomicAdd(&sh_d[lr1][hl], pd1);
        }
    }
    __syncthreads();
    {
        int row = t >> 1, hl = t & 1;
        int gr = brow + row;
        if (gr < M) {
            int hidx = gr * HEADS + (bcol >> 6) + hl;
            g_ssrc[hidx] = sh_s[row][hl];
            g_sdst[hidx] = sh_d[row][hl];
        }
    }
}

__device__ __forceinline__ float lrelu(float x) {
    return x > 0.f ? x : NEG_SLOPE * x;
}

// ---------------- warp-per-node softmax + aggregation ----------------
// Max-free softmax; bf16 gather in, bf16 out.
__global__ __launch_bounds__(256) void aggregate_kernel(
    const __nv_bfloat16* __restrict__ h16, const float* __restrict__ bias,
    __nv_bfloat16* __restrict__ out)
{
    __shared__ int   sh_src[NPB][DEG_CAP];
    __shared__ float4 sh_ex[NPB][DEG_CAP];

    int wid  = threadIdx.x >> 5;
    int lane = threadIdx.x & 31;
    int n = blockIdx.x * NPB + wid;
    if (n >= NN) return;

    int start = g_rowptr[n];
    int deg   = g_rowptr[n + 1] - start;
    bool small = (deg <= DEG_CAP);

    float4 sdv = *(const float4*)&g_sdst[n * HEADS];
    float sd0 = sdv.x, sd1 = sdv.y, sd2 = sdv.z, sd3 = sdv.w;

    // pass 1: exp + sum (warp reduce), stash per-edge exps
    float d0 = 0.f, d1 = 0.f, d2 = 0.f, d3 = 0.f;
    for (int i = lane; i < deg; i += 32) {
        int s = g_csrc[start + i];
        if (small) sh_src[wid][i] = s;
        float4 ss = *(const float4*)&g_ssrc[s * HEADS];
        float e0 = __expf(lrelu(ss.x + sd0));
        float e1 = __expf(lrelu(ss.y + sd1));
        float e2 = __expf(lrelu(ss.z + sd2));
        float e3 = __expf(lrelu(ss.w + sd3));
        d0 += e0; d1 += e1; d2 += e2; d3 += e3;
        if (small) sh_ex[wid][i] = make_float4(e0, e1, e2, e3);
        else       *(float4*)&g_ex[(size_t)(start + i) * HEADS] = make_float4(e0, e1, e2, e3);
    }
    #pragma unroll
    for (int off = 16; off > 0; off >>= 1) {
        d0 += __shfl_xor_sync(0xffffffffu, d0, off);
        d1 += __shfl_xor_sync(0xffffffffu, d1, off);
        d2 += __shfl_xor_sync(0xffffffffu, d2, off);
        d3 += __shfl_xor_sync(0xffffffffu, d3, off);
    }
    __syncwarp();

    // pass 2: weighted gather; lane owns channels [lane*8, lane*8+8) -> head = lane/8
    int hh = lane >> 3;
    float inv = 1.0f / ((hh == 0) ? d0 : (hh == 1) ? d1 : (hh == 2) ? d2 : d3);
    int coff = lane * 8;
    float a0 = 0.f, a1 = 0.f, a2 = 0.f, a3 = 0.f;
    float a4 = 0.f, a5 = 0.f, a6 = 0.f, a7 = 0.f;

    if (small) {
        #pragma unroll 4
        for (int i = 0; i < deg; i++) {
            int s = sh_src[wid][i];
            const float* ex4 = (const float*)&sh_ex[wid][i];
            float w = ex4[hh];
            uint4 v = *(const uint4*)(h16 + (size_t)s * HC + coff);
            float2 f0 = __bfloat1622float2(*(__nv_bfloat162*)&v.x);
            float2 f1 = __bfloat1622float2(*(__nv_bfloat162*)&v.y);
            float2 f2 = __bfloat1622float2(*(__nv_bfloat162*)&v.z);
            float2 f3 = __bfloat1622float2(*(__nv_bfloat162*)&v.w);
            a0 += w * f0.x; a1 += w * f0.y; a2 += w * f1.x; a3 += w * f1.y;
            a4 += w * f2.x; a5 += w * f2.y; a6 += w * f3.x; a7 += w * f3.y;
        }
    } else {
        #pragma unroll 4
        for (int i = 0; i < deg; i++) {
            int s = g_csrc[start + i];
            float w = g_ex[(size_t)(start + i) * HEADS + hh];
            uint4 v = *(const uint4*)(h16 + (size_t)s * HC + coff);
            float2 f0 = __bfloat1622float2(*(__nv_bfloat162*)&v.x);
            float2 f1 = __bfloat1622float2(*(__nv_bfloat162*)&v.y);
            float2 f2 = __bfloat1622float2(*(__nv_bfloat162*)&v.z);
            float2 f3 = __bfloat1622float2(*(__nv_bfloat162*)&v.w);
            a0 += w * f0.x; a1 += w * f0.y; a2 += w * f1.x; a3 += w * f1.y;
            a4 += w * f2.x; a5 += w * f2.y; a6 += w * f3.x; a7 += w * f3.y;
        }
    }

    float4 b0 = *(const float4*)&bias[coff];
    float4 b1 = *(const float4*)&bias[coff + 4];
    uint4 o;
    o.x = packbf(fmaxf(a0 * inv + b0.x, 0.f), fmaxf(a1 * inv + b0.y, 0.f));
    o.y = packbf(fmaxf(a2 * inv + b0.z, 0.f), fmaxf(a3 * inv + b0.w, 0.f));
    o.z = packbf(fmaxf(a4 * inv + b1.x, 0.f), fmaxf(a5 * inv + b1.y, 0.f));
    o.w = packbf(fmaxf(a6 * inv + b1.z, 0.f), fmaxf(a7 * inv + b1.w, 0.f));
    *(uint4*)(out + (size_t)n * HC + coff) = o;
}

// ---------------- pooling (bf16 input) ----------------
__global__ __launch_bounds__(256) void pool_kernel(const __nv_bfloat16* __restrict__ feat,
                                                   const int* __restrict__ batch)
{
    const int CHUNK = 64;
    int n0 = blockIdx.x * CHUNK;
    if (n0 >= NN) return;
    int t = threadIdx.x;
    int nend = min(n0 + CHUNK, NN);
    float acc = 0.f;
    int curg = batch[n0];
    for (int n = n0; n < nend; n++) {
        int g = batch[n];
        if (g != curg) {
            atomicAdd(&g_pooled[curg * HC + t], acc);
            acc = 0.f;
            curg = g;
        }
        acc += __bfloat162float(feat[(size_t)n * HC + t]);
    }
    atomicAdd(&g_pooled[curg * HC + t], acc);
}

// ---------------- MLP head (per-graph block); re-zeroes g_pooled ----------------
__global__ __launch_bounds__(128) void mlp_kernel(
    const float* __restrict__ fc1w, const float* __restrict__ fc1b,
    const float* __restrict__ bn1g, const float* __restrict__ bn1b,
    const float* __restrict__ bn1m, const float* __restrict__ bn1v,
    const float* __restrict__ fc2w, const float* __restrict__ fc2b,
    const float* __restrict__ bn2g, const float* __restrict__ bn2b,
    const float* __restrict__ bn2m, const float* __restrict__ bn2v,
    const float* __restrict__ outw, const float* __restrict__ outb,
    float* __restrict__ out)
{
    int g = blockIdx.x;
    int t = threadIdx.x;
    __shared__ float p[HC];
    __shared__ float z1[128];
    __shared__ float z2[64];
    __shared__ float red[64];

    p[t]       = g_pooled[g * HC + t];
    p[t + 128] = g_pooled[g * HC + t + 128];
    g_pooled[g * HC + t]       = 0.f;   // restore invariant
    g_pooled[g * HC + t + 128] = 0.f;
    __syncthreads();

    {
        float s = fc1b[t];
        #pragma unroll 8
        for (int k = 0; k < HC; k++) s += p[k] * fc1w[k * 128 + t];
        s = (s - bn1m[t]) * rsqrtf(bn1v[t] + BN_EPS) * bn1g[t] + bn1b[t];
        z1[t] = fmaxf(s, 0.f);
    }
    __syncthreads();

    if (t < 64) {
        float s = fc2b[t];
        #pragma unroll 8
        for (int k = 0; k < 128; k++) s += z1[k] * fc2w[k * 64 + t];
        s = (s - bn2m[t]) * rsqrtf(bn2v[t] + BN_EPS) * bn2g[t] + bn2b[t];
        z2[t] = fmaxf(s, 0.f);
    }
    __syncthreads();

    if (t < 64) red[t] = z2[t] * outw[t];
    __syncthreads();
    if (t == 0) {
        float s = 0.f;
        #pragma unroll
        for (int k = 0; k < 64; k++) s += red[k];
        out[g] = s + outb[0];
    }
}

// ---------------- launch ----------------
extern "C" void kernel_launch(void* const* d_in, const int* in_sizes, int n_in,
                              void* d_out, int out_size)
{
    const float* x     = (const float*)d_in[0];
    const int*   ei    = (const int*)  d_in[1];
    const int*   batch = (const int*)  d_in[2];
    const float* W1    = (const float*)d_in[3];
    const float* as1   = (const float*)d_in[4];
    const float* ad1   = (const float*)d_in[5];
    const float* b1    = (const float*)d_in[6];
    const float* W2    = (const float*)d_in[7];
    const float* as2   = (const float*)d_in[8];
    const float* ad2   = (const float*)d_in[9];
    const float* b2    = (const float*)d_in[10];
    const float* fc1w  = (const float*)d_in[11];
    const float* fc1b  = (const float*)d_in[12];
    const float* bn1g  = (const float*)d_in[13];
    const float* bn1b  = (const float*)d_in[14];
    const float* bn1m  = (const float*)d_in[15];
    const float* bn1v  = (const float*)d_in[16];
    const float* fc2w  = (const float*)d_in[17];
    const float* fc2b  = (const float*)d_in[18];
    const float* bn2g  = (const float*)d_in[19];
    const float* bn2b  = (const float*)d_in[20];
    const float* bn2m  = (const float*)d_in[21];
    const float* bn2v  = (const float*)d_in[22];
    const float* outw  = (const float*)d_in[23];
    const float* outb  = (const float*)d_in[24];
    float* out = (float*)d_out;

    __nv_bfloat16 *h16 = nullptr, *hB = nullptr;
    cudaGetSymbolAddress((void**)&h16, g_h16);
    cudaGetSymbolAddress((void**)&hB, g_hB);

    const int EBE = (EE + 255) / 256;

    // CSR by destination (self-loops emitted by scan; g_deg self-cleans)
    count_kernel<<<EBE, 256>>>(ei);
    scan_kernel<<<1, 1024>>>();
    fill_kernel<<<EBE, 256>>>(ei);

    dim3 ggrid((NN + 127) / 128, 2);
    const int AB = (NN + NPB - 1) / NPB;

    // GAT conv 1 (GEMM + fused attention scalars)
    gemm_tf32_kernel<<<ggrid, 256>>>(x, nullptr, W1, h16, as1, ad1, NN, FDIM);
    aggregate_kernel<<<AB, 256>>>(h16, b1, hB);

    // GAT conv 2 (A = bf16 hB)
    gemm_tf32_kernel<<<ggrid, 256>>>(nullptr, hB, W2, h16, as2, ad2, NN, HC);
    aggregate_kernel<<<AB, 256>>>(h16, b2, hB);

    // pooling + MLP head (mlp re-zeroes g_pooled)
    pool_kernel<<<(NN + 63) / 64, 256>>>(hB, batch);
    mlp_kernel<<<NG, 128>>>(fc1w, fc1b, bn1g, bn1b, bn1m, bn1v,
                            fc2w, fc2b, bn2g, bn2b, bn2m, bn2v,
                            outw, outb, out);
}